// round 16
// baseline (speedup 1.0000x reference)
#include <cuda_runtime.h>
#include <cuda_bf16.h>

// Net: x[B,2] -> fc1(9) -> ELU -> 19 x (fc 9x9 -> ELU) -> fc(2) -> log_softmax
// fp32 packed f32x2 math, NP=2 row-pairs/thread. Champion mainloop
// (wide LDS.128 loads, separate bias array, 2 chains, natural regs) +
// logit-difference epilogue.
// R16: PERSISTENT blocks — grid = 148 SMs x 8 = 1184 blocks of 64 threads
// (one full wave). Each block stages weights ONCE (fully unrolled walks),
// then grid-strides over ~7 batch chunks, prefetching the next chunk's x
// during the 20-layer compute.
// Scale domain: activations a = log2(e)*elu(z); mid W unchanged, biases *L2E,
// W1,b1 *L2E, W21diff *1/L2E.

#define THREADS 64
#define NP 2

static const int B_ROWS      = 2097152;
static const int NPAIR       = B_ROWS / 2;              // 1,048,576
static const int TOT_THREADS = NPAIR / NP;              // 524,288
static const int NCHUNK      = TOT_THREADS / THREADS;   // 8192 chunks
static const int NBLOCK      = 1184;                    // 148 SMs x 8 resident

typedef unsigned long long u64;

#define L2E  1.4426950408889634f
#define IL2E 0.6931471805599453f
#define LN2  0.6931471805599453f

// smem layout in u64 units (rows padded to 10 for LDS.128 alignment)
#define OFF_MW   0                   // 19*9*10 = 1710 ; w[l][j][k] at l*90 + j*10 + k
#define OFF_MB   1710                // 19*10 = 190    ; b[l][j] at l*10 + j (scaled L2E)
#define OFF_W1   1900                // 18 : W1[j][k] at j*2+k (scaled L2E)
#define OFF_B1   1918                // 9  (scaled L2E)
#define OFF_W21  1928                // 9 : (W21[0][k]-W21[1][k]) * IL2E
#define OFF_B21  1938                // 1 : b21[0]-b21[1]
#define SW_TOT   1940

__device__ __forceinline__ u64 pk2(float lo, float hi) {
    u64 r; asm("mov.b64 %0,{%1,%2};" : "=l"(r) : "f"(lo), "f"(hi)); return r;
}
__device__ __forceinline__ void upk2(float& lo, float& hi, u64 v) {
    asm("mov.b64 {%0,%1},%2;" : "=f"(lo), "=f"(hi) : "l"(v));
}
__device__ __forceinline__ u64 ffma2(u64 a, u64 b, u64 c) {
    u64 d; asm("fma.rn.f32x2 %0,%1,%2,%3;" : "=l"(d) : "l"(a), "l"(b), "l"(c)); return d;
}
__device__ __forceinline__ float ex2(float x) {
    float r; asm("ex2.approx.ftz.f32 %0, %1;" : "=f"(r) : "f"(x)); return r;
}
__device__ __forceinline__ float lg2(float x) {
    float r; asm("lg2.approx.ftz.f32 %0, %1;" : "=f"(r) : "f"(x)); return r;
}

// scale-domain ELU, scalar form (3 issues per half, no pack/unpack MOVs):
//   r = fmaf(EX2(-|a|), L2E, -L2E);  out = max(a, r)
__device__ __forceinline__ u64 elu2s(u64 v) {
    float lo, hi; upk2(lo, hi, v);
    float rlo = fmaf(ex2(-fabsf(lo)), L2E, -L2E);
    float rhi = fmaf(ex2(-fabsf(hi)), L2E, -L2E);
    return pk2(fmaxf(lo, rlo), fmaxf(hi, rhi));
}

// log_softmax from the logit difference d = l0 - l1 (stable):
//   o0 = min(d,0) - LN2*lg2(1 + 2^(-|d|*L2E));   o1 = o0 - d
__device__ __forceinline__ void lsm_d(float d, float& o0, float& o1) {
    float u = ex2(-fabsf(d * L2E));
    o0 = fmaf(lg2(1.0f + u), -LN2, fminf(d, 0.0f));
    o1 = o0 - d;
}

// one 9x9 mid layer + scale-domain ELU, in -> out  (champion structure)
__device__ __forceinline__ void mid_layer(const u64* __restrict__ wl,
                                          const u64* __restrict__ bl,
                                          u64 (&in)[NP][9], u64 (&out)[NP][9])
{
    ulonglong2 b01 = *reinterpret_cast<const ulonglong2*>(bl + 0);
    ulonglong2 b23 = *reinterpret_cast<const ulonglong2*>(bl + 2);
    ulonglong2 b45 = *reinterpret_cast<const ulonglong2*>(bl + 4);
    ulonglong2 b67 = *reinterpret_cast<const ulonglong2*>(bl + 6);
    u64 b8 = bl[8];
    u64 bias[9] = {b01.x, b01.y, b23.x, b23.y, b45.x, b45.y, b67.x, b67.y, b8};

#pragma unroll
    for (int j = 0; j < 9; j++) {
        const u64* wr = wl + j * 10;
        ulonglong2 w01 = *reinterpret_cast<const ulonglong2*>(wr + 0);
        ulonglong2 w23 = *reinterpret_cast<const ulonglong2*>(wr + 2);
        ulonglong2 w45 = *reinterpret_cast<const ulonglong2*>(wr + 4);
        ulonglong2 w67 = *reinterpret_cast<const ulonglong2*>(wr + 6);
        u64 w8 = wr[8];
        u64 w[9] = {w01.x, w01.y, w23.x, w23.y, w45.x, w45.y, w67.x, w67.y, w8};

        u64 acc[NP];
#pragma unroll
        for (int p = 0; p < NP; p++) acc[p] = bias[j];
#pragma unroll
        for (int k = 0; k < 9; k++) {
#pragma unroll
            for (int p = 0; p < NP; p++) acc[p] = ffma2(w[k], in[p][k], acc[p]);
        }
#pragma unroll
        for (int p = 0; p < NP; p++) out[p][j] = elu2s(acc[p]);
    }
}

__global__ void __launch_bounds__(THREADS)
mlp_kernel(const float* __restrict__ x,
           const float* __restrict__ W1,  const float* __restrict__ b1,
           const float* __restrict__ Wm,  const float* __restrict__ bm,
           const float* __restrict__ W21, const float* __restrict__ b21,
           float* __restrict__ out)
{
    __shared__ __align__(16) u64 sw[SW_TOT];
    const int t = threadIdx.x;

    // -------- one-time staging (division-free, fully unrolled walks) --------
    {
        int j = t / 9, k = t % 9;                 // element e = t of 81
        u64* dst = &sw[OFF_MW + j * 10 + k];
        const float* src = Wm + t;
#pragma unroll
        for (int l = 0; l < 19; l++) {
            float v = src[l * 81];
            dst[l * 90] = pk2(v, v);
        }
    }
    if (t < 17) {                                 // elements e = 64..80
        int e = t + 64;
        int j = e / 9, k = e % 9;
        u64* dst = &sw[OFF_MW + j * 10 + k];
        const float* src = Wm + e;
#pragma unroll
        for (int l = 0; l < 19; l++) {
            float v = src[l * 81];
            dst[l * 90] = pk2(v, v);
        }
    }
    if (t >= 32 && t < 41) {                      // mid biases, j = t-32
        int j = t - 32;
#pragma unroll
        for (int l = 0; l < 19; l++) {
            float v = bm[l * 9 + j] * L2E;
            sw[OFF_MB + l * 10 + j] = pk2(v, v);
        }
    }
    if (t >= 48 && t < 57) {                      // fc1, j = t-48
        int j = t - 48;
        float w0 = W1[j * 2 + 0] * L2E;
        float w1 = W1[j * 2 + 1] * L2E;
        float bb = b1[j] * L2E;
        sw[OFF_W1 + j * 2 + 0] = pk2(w0, w0);
        sw[OFF_W1 + j * 2 + 1] = pk2(w1, w1);
        sw[OFF_B1 + j]         = pk2(bb, bb);
    }
    if (t >= 17 && t < 26) {                      // W21 logit-difference
        int i = t - 17;
        float v = (W21[i] - W21[9 + i]) * IL2E;
        sw[OFF_W21 + i] = pk2(v, v);
    }
    if (t == 26) {
        float v = b21[0] - b21[1];
        sw[OFF_B21] = pk2(v, v);
    }
    __syncthreads();

    // -------- persistent chunk loop with x-prefetch --------
    int c = blockIdx.x;
    int p0 = c * THREADS + t;
    int p1 = p0 + TOT_THREADS;
    float4 xin0 = reinterpret_cast<const float4*>(x)[p0];
    float4 xin1 = reinterpret_cast<const float4*>(x)[p1];

#pragma unroll 1
    for (;;) {
        u64 h[NP][9], g[NP][9];

        // ---- fc1 (pre-scaled by L2E) + ELU ---- (consumes xin0/xin1)
        {
            u64 x0 = pk2(xin0.x, xin0.z);
            u64 x1 = pk2(xin0.y, xin0.w);
            u64 y0 = pk2(xin1.x, xin1.z);
            u64 y1 = pk2(xin1.y, xin1.w);
#pragma unroll
            for (int j = 0; j < 9; j++) {
                u64 wa = sw[OFF_W1 + j * 2 + 0];
                u64 wb = sw[OFF_W1 + j * 2 + 1];
                u64 bb = sw[OFF_B1 + j];
                u64 a0 = ffma2(wa, x0, bb);
                u64 a1 = ffma2(wa, y0, bb);
                a0 = ffma2(wb, x1, a0);
                a1 = ffma2(wb, y1, a1);
                h[0][j] = elu2s(a0);
                h[1][j] = elu2s(a1);
            }
        }

        // store indices for this chunk; prefetch next chunk's x
        int s0 = p0, s1 = p1;
        int cn = c + NBLOCK;
        bool more = cn < NCHUNK;
        if (more) {
            c  = cn;
            p0 = c * THREADS + t;
            p1 = p0 + TOT_THREADS;
            xin0 = reinterpret_cast<const float4*>(x)[p0];
            xin1 = reinterpret_cast<const float4*>(x)[p1];
        }

        // ---- 19 mid layers: 9 x (h->g, g->h) + final h->g ----
#pragma unroll 1
        for (int l = 0; l < 9; l++) {
            mid_layer(&sw[OFF_MW + (2 * l)     * 90], &sw[OFF_MB + (2 * l)     * 10], h, g);
            mid_layer(&sw[OFF_MW + (2 * l + 1) * 90], &sw[OFF_MB + (2 * l + 1) * 10], g, h);
        }
        mid_layer(&sw[OFF_MW + 18 * 90], &sw[OFF_MB + 18 * 10], h, g);

        // ---- output: logit difference d = l0 - l1, then stable log_softmax ----
#pragma unroll
        for (int p = 0; p < NP; p++) {
            u64 dacc = ffma2(sw[OFF_W21 + 8], g[p][8], sw[OFF_B21]);
#pragma unroll
            for (int k = 0; k < 8; k++)
                dacc = ffma2(sw[OFF_W21 + k], g[p][k], dacc);

            float dA, dB;
            upk2(dA, dB, dacc);

            float4 o;
            lsm_d(dA, o.x, o.y);
            lsm_d(dB, o.z, o.w);
            reinterpret_cast<float4*>(out)[p ? s1 : s0] = o;
        }

        if (!more) break;
    }
}

extern "C" void kernel_launch(void* const* d_in, const int* in_sizes, int n_in,
                              void* d_out, int out_size)
{
    const float* x   = (const float*)d_in[0];
    const float* W1  = (const float*)d_in[1];
    const float* b1  = (const float*)d_in[2];
    const float* Wm  = (const float*)d_in[3];
    const float* bm  = (const float*)d_in[4];
    const float* W21 = (const float*)d_in[5];
    const float* b21 = (const float*)d_in[6];
    float*       out = (float*)d_out;

    mlp_kernel<<<NBLOCK, THREADS>>>(x, W1, b1, Wm, bm, W21, b21, out);
}

// round 17
// speedup vs baseline: 1.4508x; 1.4508x over previous
#include <cuda_runtime.h>
#include <cuda_bf16.h>

// Net: x[B,2] -> fc1(9) -> ELU -> 19 x (fc 9x9 -> ELU) -> fc(2) -> log_softmax
// fp32 packed f32x2 math, NP=2 row-pairs/thread. Champion mainloop
// (wide LDS.128 loads, separate bias array, 2 chains, natural regs, 64-thr
// de-phased blocks) + logit-difference epilogue.
// R17: single kernel, one chunk per block (grid 8192); division-free staging
// with FULLY UNROLLED 19-layer walks (all staging LDGs in flight at once).
// Scale domain: activations a = log2(e)*elu(z); mid W unchanged, biases *L2E,
// W1,b1 *L2E, W21diff *1/L2E.

#define THREADS 64
#define NP 2

static const int B_ROWS      = 2097152;
static const int NPAIR       = B_ROWS / 2;              // 1,048,576
static const int TOT_THREADS = NPAIR / NP;              // 524,288
static const int NBLOCK      = TOT_THREADS / THREADS;   // 8192

typedef unsigned long long u64;

#define L2E  1.4426950408889634f
#define IL2E 0.6931471805599453f
#define LN2  0.6931471805599453f

// smem layout in u64 units (rows padded to 10 for LDS.128 alignment)
#define OFF_MW   0                   // 19*9*10 = 1710 ; w[l][j][k] at l*90 + j*10 + k
#define OFF_MB   1710                // 19*10 = 190    ; b[l][j] at l*10 + j (scaled L2E)
#define OFF_W1   1900                // 18 : W1[j][k] at j*2+k (scaled L2E)
#define OFF_B1   1918                // 9  (scaled L2E)
#define OFF_W21  1928                // 9 : (W21[0][k]-W21[1][k]) * IL2E
#define OFF_B21  1938                // 1 : b21[0]-b21[1]
#define SW_TOT   1940

__device__ __forceinline__ u64 pk2(float lo, float hi) {
    u64 r; asm("mov.b64 %0,{%1,%2};" : "=l"(r) : "f"(lo), "f"(hi)); return r;
}
__device__ __forceinline__ void upk2(float& lo, float& hi, u64 v) {
    asm("mov.b64 {%0,%1},%2;" : "=f"(lo), "=f"(hi) : "l"(v));
}
__device__ __forceinline__ u64 ffma2(u64 a, u64 b, u64 c) {
    u64 d; asm("fma.rn.f32x2 %0,%1,%2,%3;" : "=l"(d) : "l"(a), "l"(b), "l"(c)); return d;
}
__device__ __forceinline__ float ex2(float x) {
    float r; asm("ex2.approx.ftz.f32 %0, %1;" : "=f"(r) : "f"(x)); return r;
}
__device__ __forceinline__ float lg2(float x) {
    float r; asm("lg2.approx.ftz.f32 %0, %1;" : "=f"(r) : "f"(x)); return r;
}

// scale-domain ELU, scalar form (3 issues per half, no pack/unpack MOVs):
//   r = fmaf(EX2(-|a|), L2E, -L2E);  out = max(a, r)
__device__ __forceinline__ u64 elu2s(u64 v) {
    float lo, hi; upk2(lo, hi, v);
    float rlo = fmaf(ex2(-fabsf(lo)), L2E, -L2E);
    float rhi = fmaf(ex2(-fabsf(hi)), L2E, -L2E);
    return pk2(fmaxf(lo, rlo), fmaxf(hi, rhi));
}

// log_softmax from the logit difference d = l0 - l1 (stable):
//   o0 = min(d,0) - LN2*lg2(1 + 2^(-|d|*L2E));   o1 = o0 - d
__device__ __forceinline__ void lsm_d(float d, float& o0, float& o1) {
    float u = ex2(-fabsf(d * L2E));
    o0 = fmaf(lg2(1.0f + u), -LN2, fminf(d, 0.0f));
    o1 = o0 - d;
}

// one 9x9 mid layer + scale-domain ELU, in -> out  (champion structure)
__device__ __forceinline__ void mid_layer(const u64* __restrict__ wl,
                                          const u64* __restrict__ bl,
                                          u64 (&in)[NP][9], u64 (&out)[NP][9])
{
    ulonglong2 b01 = *reinterpret_cast<const ulonglong2*>(bl + 0);
    ulonglong2 b23 = *reinterpret_cast<const ulonglong2*>(bl + 2);
    ulonglong2 b45 = *reinterpret_cast<const ulonglong2*>(bl + 4);
    ulonglong2 b67 = *reinterpret_cast<const ulonglong2*>(bl + 6);
    u64 b8 = bl[8];
    u64 bias[9] = {b01.x, b01.y, b23.x, b23.y, b45.x, b45.y, b67.x, b67.y, b8};

#pragma unroll
    for (int j = 0; j < 9; j++) {
        const u64* wr = wl + j * 10;
        ulonglong2 w01 = *reinterpret_cast<const ulonglong2*>(wr + 0);
        ulonglong2 w23 = *reinterpret_cast<const ulonglong2*>(wr + 2);
        ulonglong2 w45 = *reinterpret_cast<const ulonglong2*>(wr + 4);
        ulonglong2 w67 = *reinterpret_cast<const ulonglong2*>(wr + 6);
        u64 w8 = wr[8];
        u64 w[9] = {w01.x, w01.y, w23.x, w23.y, w45.x, w45.y, w67.x, w67.y, w8};

        u64 acc[NP];
#pragma unroll
        for (int p = 0; p < NP; p++) acc[p] = bias[j];
#pragma unroll
        for (int k = 0; k < 9; k++) {
#pragma unroll
            for (int p = 0; p < NP; p++) acc[p] = ffma2(w[k], in[p][k], acc[p]);
        }
#pragma unroll
        for (int p = 0; p < NP; p++) out[p][j] = elu2s(acc[p]);
    }
}

__global__ void __launch_bounds__(THREADS)
mlp_kernel(const float* __restrict__ x,
           const float* __restrict__ W1,  const float* __restrict__ b1,
           const float* __restrict__ Wm,  const float* __restrict__ bm,
           const float* __restrict__ W21, const float* __restrict__ b21,
           float* __restrict__ out)
{
    __shared__ __align__(16) u64 sw[SW_TOT];
    const int t = threadIdx.x;
    const int gtid = blockIdx.x * THREADS + t;

    // Input loads first: DRAM latency overlaps staging.
    float4 xin[NP];
    int    pidx[NP];
#pragma unroll
    for (int p = 0; p < NP; p++) {
        pidx[p] = gtid + p * TOT_THREADS;
        xin[p]  = reinterpret_cast<const float4*>(x)[pidx[p]];
    }

    // -------- division-free staging, FULLY UNROLLED walks --------
    // Mid W element e = t of 81; (j,k) computed once, 19 independent LDGs.
    {
        int j = t / 9, k = t % 9;
        u64* dst = &sw[OFF_MW + j * 10 + k];
        const float* src = Wm + t;
        float v[19];
#pragma unroll
        for (int l = 0; l < 19; l++) v[l] = src[l * 81];
#pragma unroll
        for (int l = 0; l < 19; l++) dst[l * 90] = pk2(v[l], v[l]);
    }
    if (t < 17) {                                 // elements e = 64..80
        int e = t + 64;
        int j = e / 9, k = e % 9;
        u64* dst = &sw[OFF_MW + j * 10 + k];
        const float* src = Wm + e;
        float v[19];
#pragma unroll
        for (int l = 0; l < 19; l++) v[l] = src[l * 81];
#pragma unroll
        for (int l = 0; l < 19; l++) dst[l * 90] = pk2(v[l], v[l]);
    }
    if (t >= 32 && t < 41) {                      // mid biases, j = t-32
        int j = t - 32;
        float v[19];
#pragma unroll
        for (int l = 0; l < 19; l++) v[l] = bm[l * 9 + j] * L2E;
#pragma unroll
        for (int l = 0; l < 19; l++) sw[OFF_MB + l * 10 + j] = pk2(v[l], v[l]);
    }
    if (t >= 48 && t < 57) {                      // fc1, j = t-48
        int j = t - 48;
        float w0 = W1[j * 2 + 0] * L2E;
        float w1 = W1[j * 2 + 1] * L2E;
        float bb = b1[j] * L2E;
        sw[OFF_W1 + j * 2 + 0] = pk2(w0, w0);
        sw[OFF_W1 + j * 2 + 1] = pk2(w1, w1);
        sw[OFF_B1 + j]         = pk2(bb, bb);
    }
    if (t >= 17 && t < 26) {                      // W21 logit-difference
        int i = t - 17;
        float v = (W21[i] - W21[9 + i]) * IL2E;
        sw[OFF_W21 + i] = pk2(v, v);
    }
    if (t == 26) {
        float v = b21[0] - b21[1];
        sw[OFF_B21] = pk2(v, v);
    }
    __syncthreads();

    u64 h[NP][9], g[NP][9];

    // ---- fc1 (pre-scaled by L2E) + ELU ----
#pragma unroll
    for (int p = 0; p < NP; p++) {
        u64 x0 = pk2(xin[p].x, xin[p].z);
        u64 x1 = pk2(xin[p].y, xin[p].w);
#pragma unroll
        for (int j = 0; j < 9; j++) {
            u64 acc = ffma2(sw[OFF_W1 + j * 2 + 0], x0, sw[OFF_B1 + j]);
            acc     = ffma2(sw[OFF_W1 + j * 2 + 1], x1, acc);
            h[p][j] = elu2s(acc);
        }
    }

    // ---- 19 mid layers: 9 x (h->g, g->h) + final h->g ----
#pragma unroll 1
    for (int l = 0; l < 9; l++) {
        mid_layer(&sw[OFF_MW + (2 * l)     * 90], &sw[OFF_MB + (2 * l)     * 10], h, g);
        mid_layer(&sw[OFF_MW + (2 * l + 1) * 90], &sw[OFF_MB + (2 * l + 1) * 10], g, h);
    }
    mid_layer(&sw[OFF_MW + 18 * 90], &sw[OFF_MB + 18 * 10], h, g);

    // ---- output: logit difference d = l0 - l1, then stable log_softmax ----
#pragma unroll
    for (int p = 0; p < NP; p++) {
        u64 dacc = ffma2(sw[OFF_W21 + 8], g[p][8], sw[OFF_B21]);
#pragma unroll
        for (int k = 0; k < 8; k++)
            dacc = ffma2(sw[OFF_W21 + k], g[p][k], dacc);

        float dA, dB;
        upk2(dA, dB, dacc);

        float4 o;
        lsm_d(dA, o.x, o.y);
        lsm_d(dB, o.z, o.w);
        reinterpret_cast<float4*>(out)[pidx[p]] = o;
    }
}

extern "C" void kernel_launch(void* const* d_in, const int* in_sizes, int n_in,
                              void* d_out, int out_size)
{
    const float* x   = (const float*)d_in[0];
    const float* W1  = (const float*)d_in[1];
    const float* b1  = (const float*)d_in[2];
    const float* Wm  = (const float*)d_in[3];
    const float* bm  = (const float*)d_in[4];
    const float* W21 = (const float*)d_in[5];
    const float* b21 = (const float*)d_in[6];
    float*       out = (float*)d_out;

    mlp_kernel<<<NBLOCK, THREADS>>>(x, W1, b1, Wm, bm, W21, b21, out);
}